// round 6
// baseline (speedup 1.0000x reference)
#include <cuda_runtime.h>
#include <cuda_fp16.h>

// Problem constants (fixed shapes for this problem)
#define Nn    50000
#define FIN   128
#define D1    128           // H1*C1
#define NC    16
#define EMAX  1600000
#define ETMAX (EMAX + Nn)

// ---------------- scratch (device globals; no allocation allowed) ------------
__device__ ulonglong2 g_w1d[128 * 32 * 2];  // [k][c4][2]: dup-pair packed w1
__device__ float4     g_w2t4[(D1 / 4) * NC];
__device__ __half2    g_xw1h[Nn * 64];      // fp16 gather payload (layer 1)
__device__ float      g_out1[Nn * D1];
__device__ float      g_asrc1[Nn * 2];
__device__ float      g_adst1[Nn * 2];
__device__ __half     g_xw2h[Nn * NC];      // fp16 gather payload (layer 2)
__device__ float      g_asrc2[Nn];
__device__ float      g_adst2[Nn];
__device__ unsigned   g_cnt[Nn];            // invariant: zero at kernel_launch entry
__device__ unsigned   g_off[Nn + 1];
__device__ unsigned   g_cur[Nn];
__device__ int        g_adj[ETMAX];         // CSR by dst: src node ids

__device__ __forceinline__ float lrelu(float a) { return a > 0.f ? a : 0.2f * a; }

__device__ __forceinline__ unsigned long long ffma2(unsigned long long a,
                                                    unsigned long long b,
                                                    unsigned long long c) {
    unsigned long long d;
    asm("fma.rn.f32x2 %0, %1, %2, %3;" : "=l"(d) : "l"(a), "l"(b), "l"(c));
    return d;
}
__device__ __forceinline__ float2 unpk2(unsigned long long v) {
    unsigned lo, hi;
    asm("mov.b64 {%0, %1}, %2;" : "=r"(lo), "=r"(hi) : "l"(v));
    return make_float2(__uint_as_float(lo), __uint_as_float(hi));
}

// ---------------- prep (weight repack) + histogram fused ---------------------
__global__ void k_prephist(const float* __restrict__ w1, const float* __restrict__ w2,
                           const int* __restrict__ ei, int E, int ET) {
    int i = blockIdx.x * blockDim.x + threadIdx.x;
    if (i < FIN * D1) {
        int c = i / FIN, k = i % FIN;             // w1: [D1][FIN] row-major
        float v = w1[i];
        float* p = (float*)g_w1d + (k * 32 + (c >> 2)) * 8 + (c & 3) * 2;
        p[0] = v; p[1] = v;                       // duplicated pair for f32x2
    }
    if (i < NC * D1) {
        int o = i / D1, k = i % D1;               // w2: [NC][D1]
        ((float*)g_w2t4)[((k >> 2) * NC + o) * 4 + (k & 3)] = w2[i];
    }
    if (i < ET) {
        int d = (i < E) ? ei[E + i] : (i - E);
        atomicAdd(&g_cnt[d], 1u);                 // no return use -> REDG
    }
}

// ---------------- scan (also re-zeroes g_cnt for the next call) --------------
__global__ void k_scan(int n) {
    __shared__ unsigned ssum[1024];
    int t = threadIdx.x;
    int chunk = (n + 1023) >> 10;
    int b = t * chunk;
    int e = min(b + chunk, n);
    unsigned sum = 0;
    for (int i = b; i < e; i++) sum += g_cnt[i];
    ssum[t] = sum;
    __syncthreads();
    for (int o = 1; o < 1024; o <<= 1) {
        unsigned v = (t >= o) ? ssum[t - o] : 0u;
        __syncthreads();
        ssum[t] += v;
        __syncthreads();
    }
    unsigned run = (t == 0) ? 0u : ssum[t - 1];
    for (int i = b; i < e; i++) {
        unsigned c = g_cnt[i];
        g_cnt[i] = 0u;                            // restore invariant
        g_off[i] = run;
        g_cur[i] = run;
        run += c;
    }
    if (t == 0) g_off[n] = ssum[1023];
}

__global__ void k_scatter(const int* __restrict__ ei, int E, int ET) {
    int e = blockIdx.x * blockDim.x + threadIdx.x;
    if (e >= ET) return;
    int s, d;
    if (e < E) { s = ei[e]; d = ei[E + e]; } else { s = d = e - E; }
    unsigned pos = atomicAdd(&g_cur[d], 1u);
    g_adj[pos] = s;
}

// ------- layer-1 GEMM (f32x2 packed FMA) + att1 dots + fp16 payload ----------
__global__ __launch_bounds__(256) void k_gemm1(const float* __restrict__ x,
                                               const float* __restrict__ att_s,
                                               const float* __restrict__ att_d, int n) {
    __shared__ float xs[128 * 36];   // pad 36: 16B-aligned float4 rows
    int tid = threadIdx.x;
    int nb  = blockIdx.x * 32;
    for (int idx = tid; idx < 32 * 128; idx += 256) {
        int node = idx >> 7, k = idx & 127;
        xs[k * 36 + node] = (nb + node < n) ? x[(nb + node) * FIN + k] : 0.f;
    }
    __syncthreads();
    int c4 = tid & 31;     // channels c4*4 .. c4*4+3 (lane id)
    int ng = tid >> 5;     // nodes ng*4 .. ng*4+3 (warp id)
    unsigned long long acc[4][2];    // [channel][node-pair]
#pragma unroll
    for (int c = 0; c < 4; c++) { acc[c][0] = 0ull; acc[c][1] = 0ull; }
#pragma unroll 4
    for (int k = 0; k < 128; k++) {
        ulonglong2 wa = g_w1d[(k * 32 + c4) * 2 + 0];  // {c0,c0},{c1,c1}
        ulonglong2 wb = g_w1d[(k * 32 + c4) * 2 + 1];  // {c2,c2},{c3,c3}
        ulonglong2 xv = *(const ulonglong2*)&xs[k * 36 + ng * 4];  // {n0,n1},{n2,n3}
        acc[0][0] = ffma2(wa.x, xv.x, acc[0][0]); acc[0][1] = ffma2(wa.x, xv.y, acc[0][1]);
        acc[1][0] = ffma2(wa.y, xv.x, acc[1][0]); acc[1][1] = ffma2(wa.y, xv.y, acc[1][1]);
        acc[2][0] = ffma2(wb.x, xv.x, acc[2][0]); acc[2][1] = ffma2(wb.x, xv.y, acc[2][1]);
        acc[3][0] = ffma2(wb.y, xv.x, acc[3][0]); acc[3][1] = ffma2(wb.y, xv.y, acc[3][1]);
    }
    float af[4][4];                  // [node][channel]
#pragma unroll
    for (int c = 0; c < 4; c++) {
        float2 p0 = unpk2(acc[c][0]);
        float2 p1 = unpk2(acc[c][1]);
        af[0][c] = p0.x; af[1][c] = p0.y; af[2][c] = p1.x; af[3][c] = p1.y;
    }
    // fp16 gather payload
#pragma unroll
    for (int i = 0; i < 4; i++) {
        int node = nb + ng * 4 + i;
        if (node < n) {
            g_xw1h[node * 64 + c4 * 2 + 0] = __floats2half2_rn(af[i][0], af[i][1]);
            g_xw1h[node * 64 + c4 * 2 + 1] = __floats2half2_rn(af[i][2], af[i][3]);
        }
    }
    // fused attention dots: reduce within 16-lane halves (= heads)
    float4 as4 = *(const float4*)&att_s[c4 * 4];
    float4 ad4 = *(const float4*)&att_d[c4 * 4];
#pragma unroll
    for (int i = 0; i < 4; i++) {
        float ps = af[i][0] * as4.x + af[i][1] * as4.y + af[i][2] * as4.z + af[i][3] * as4.w;
        float pd = af[i][0] * ad4.x + af[i][1] * ad4.y + af[i][2] * ad4.z + af[i][3] * ad4.w;
#pragma unroll
        for (int o = 8; o >= 1; o >>= 1) {
            ps += __shfl_xor_sync(0xffffffffu, ps, o);
            pd += __shfl_xor_sync(0xffffffffu, pd, o);
        }
        int node = nb + ng * 4 + i;
        if ((c4 & 15) == 0 && node < n) {
            int h = c4 >> 4;
            g_asrc1[node * 2 + h] = ps;
            g_adst1[node * 2 + h] = pd;
        }
    }
}

// ------- layer-1 fused softmax+aggregate: warp/dst, 16-edge pipelined chunks -
__global__ void k_edge1(const float* __restrict__ b1, int n) {
    int gt = blockIdx.x * blockDim.x + threadIdx.x;
    int d  = gt >> 5;
    if (d >= n) return;
    int lane = gt & 31, h = lane >> 4, sub = lane & 15;
    int beg = (int)g_off[d], end = (int)g_off[d + 1];
    float adh = g_adst1[d * 2 + h];
    float4 acc = make_float4(0.f, 0.f, 0.f, 0.f);
    float s = 0.f;
    // preload chunk 0: lanes 0-15 compute e(head0), lanes 16-31 e(head1), same 16 edges
    int base = beg;
    int msrc = 0; float ex = 0.f;
    {
        int i0 = base + sub;
        if (i0 < end) {
            msrc = g_adj[i0];
            ex = __expf(lrelu(g_asrc1[msrc * 2 + h] + adh));
        }
    }
    while (base < end) {
        int nbase = base + 16;
        int nsrc = 0; float nex = 0.f;
        if (nbase < end) {              // software-pipeline next chunk's dep chain
            int i1 = nbase + sub;
            if (i1 < end) {
                nsrc = g_adj[i1];
                nex = __expf(lrelu(g_asrc1[nsrc * 2 + h] + adh));
            }
        }
        s += ex;
        int cnt = min(16, end - base);
#pragma unroll 8
        for (int j = 0; j < cnt; j++) {
            int   src  = __shfl_sync(0xffffffffu, msrc, j);
            float coef = __shfl_sync(0xffffffffu, ex, j + (h << 4));
            uint2 p = *(const uint2*)&g_xw1h[src * 64 + lane * 2];
            float2 v01 = __half22float2(*(__half2*)&p.x);
            float2 v23 = __half22float2(*(__half2*)&p.y);
            acc.x += v01.x * coef; acc.y += v01.y * coef;
            acc.z += v23.x * coef; acc.w += v23.y * coef;
        }
        msrc = nsrc; ex = nex; base = nbase;
    }
#pragma unroll
    for (int o = 8; o >= 1; o >>= 1)    // per-half sums: lanes<16 -> s0, >=16 -> s1
        s += __shfl_xor_sync(0xffffffffu, s, o);
    float r = 1.f / (s + 1e-16f);
    float4 bb = *(const float4*)&b1[lane * 4];
    *(float4*)&g_out1[d * D1 + lane * 4] =
        make_float4(acc.x * r + bb.x, acc.y * r + bb.y, acc.z * r + bb.z, acc.w * r + bb.w);
}

// ---------------- layer-2 GEMM (relu fused on load) + att2 dots --------------
__global__ void k_gemm2(const float* __restrict__ att_s, const float* __restrict__ att_d, int n) {
    __shared__ float xs[8 * 132];
    int t  = threadIdx.x;            // 128 threads = 8 nodes x 16 outs
    int nb = blockIdx.x * 8;
#pragma unroll
    for (int i = 0; i < 8; i++) {
        int node = nb + i;
        float v = (node < n) ? g_out1[node * D1 + t] : 0.f;
        xs[i * 132 + t] = fmaxf(v, 0.f);     // relu
    }
    __syncthreads();
    int ni = t >> 4;
    int o  = t & 15;
    float a0 = 0.f, a1 = 0.f, a2 = 0.f, a3 = 0.f;
#pragma unroll
    for (int k4 = 0; k4 < D1 / 4; k4 += 4) {
#pragma unroll
        for (int u = 0; u < 4; u++) {
            float4 w  = g_w2t4[(k4 + u) * NC + o];
            float4 xv = *(const float4*)&xs[ni * 132 + (k4 + u) * 4];
            float p = xv.x * w.x + xv.y * w.y + xv.z * w.z + xv.w * w.w;
            if (u == 0) a0 += p; else if (u == 1) a1 += p; else if (u == 2) a2 += p; else a3 += p;
        }
    }
    float acc = (a0 + a1) + (a2 + a3);
    int node = nb + ni;
    if (node < n) g_xw2h[node * NC + o] = __float2half(acc);
    float ps = acc * att_s[o];
    float pd = acc * att_d[o];
#pragma unroll
    for (int j = 8; j >= 1; j >>= 1) {
        ps += __shfl_xor_sync(0xffffffffu, ps, j);
        pd += __shfl_xor_sync(0xffffffffu, pd, j);
    }
    if (o == 0 && node < n) { g_asrc2[node] = ps; g_adst2[node] = pd; }
}

// ---------------- layer-2 fused softmax+aggregate (warp per dst) -------------
__global__ void k_edge2(const float* __restrict__ b2, float* __restrict__ out, int n) {
    int gt = blockIdx.x * blockDim.x + threadIdx.x;
    int d  = gt >> 5;
    if (d >= n) return;
    int lane = gt & 31;
    int beg = (int)g_off[d], end = (int)g_off[d + 1];
    float add = g_adst2[d];
    int half = lane >> 4;
    int c    = lane & 15;
    float acc = 0.f, s = 0.f;
    for (int base = beg; base < end; base += 32) {
        int myi = base + lane;
        float ev = 0.f;
        int msrc = 0;
        if (myi < end) {
            msrc = g_adj[myi];
            ev = __expf(lrelu(g_asrc2[msrc] + add));
        }
        s += ev;
        int cnt = min(32, end - base);
#pragma unroll 4
        for (int j = 0; j < cnt; j += 2) {
            int jj = j + half;                  // lanes 0-15 edge j, 16-31 edge j+1
            int   src = __shfl_sync(0xffffffffu, msrc, jj & 31);
            float e   = __shfl_sync(0xffffffffu, ev, jj & 31);
            if (jj < cnt)
                acc += __half2float(g_xw2h[src * NC + c]) * e;
        }
    }
#pragma unroll
    for (int o = 16; o >= 1; o >>= 1)
        s += __shfl_xor_sync(0xffffffffu, s, o);
    acc += __shfl_xor_sync(0xffffffffu, acc, 16);
    if (half == 0) {
        float r = 1.f / (s + 1e-16f);
        out[d * NC + c] = acc * r + b2[c];
    }
}

// ---------------- launcher ----------------------------------------------------
extern "C" void kernel_launch(void* const* d_in, const int* in_sizes, int n_in,
                              void* d_out, int out_size) {
    const float* x   = (const float*)d_in[0];
    const int*   ei  = (const int*)d_in[1];      // int32
    const float* w1  = (const float*)d_in[2];
    const float* as1 = (const float*)d_in[3];
    const float* ad1 = (const float*)d_in[4];
    const float* b1  = (const float*)d_in[5];
    const float* w2  = (const float*)d_in[6];
    const float* as2 = (const float*)d_in[7];
    const float* ad2 = (const float*)d_in[8];
    const float* b2  = (const float*)d_in[9];
    float* out = (float*)d_out;

    int n  = in_sizes[0] / FIN;     // 50000
    int E  = in_sizes[1] / 2;       // 1600000
    int ET = E + n;                 // 1650000

    k_prephist<<<(ET + 255) / 256, 256>>>(w1, w2, ei, E, ET);
    k_scan<<<1, 1024>>>(n);
    k_scatter<<<(ET + 255) / 256, 256>>>(ei, E, ET);

    // layer 1 (att1 dots + fp16 payload fused into gemm1)
    k_gemm1<<<(n + 31) / 32, 256>>>(x, as1, ad1, n);
    k_edge1<<<(n * 32 + 255) / 256, 256>>>(b1, n);

    // layer 2
    k_gemm2<<<(n + 7) / 8, 128>>>(as2, ad2, n);
    k_edge2<<<(n * 32 + 255) / 256, 256>>>(b2, out, n);
}

// round 7
// speedup vs baseline: 1.1631x; 1.1631x over previous
#include <cuda_runtime.h>
#include <cuda_fp16.h>

// Problem constants (fixed shapes for this problem)
#define Nn    50000
#define FIN   128
#define D1    128           // H1*C1
#define NC    16
#define EMAX  1600000
#define ETMAX (EMAX + Nn)

// dynamic smem partition for k_gemm1h (floats)
#define WS_STRIDE 132                 // 128 + 4: conflict-free LDS.128, 16B-aligned
#define XS_STRIDE 36
#define WS_FLOATS (128 * WS_STRIDE)   // 16896
#define XS_FLOATS (128 * XS_STRIDE)   // 4608
#define GEMM1_SMEM ((WS_FLOATS + XS_FLOATS) * 4)

// ---------------- scratch (device globals; no allocation allowed) ------------
__device__ float4     g_w2t4[(D1 / 4) * NC];
__device__ __half2    g_xw1h[Nn * 64];      // fp16 gather payload (layer 1)
__device__ float      g_out1[Nn * D1];
__device__ float      g_asrc1[Nn * 2];
__device__ float      g_adst1[Nn * 2];
__device__ __half     g_xw2h[Nn * NC];      // fp16 gather payload (layer 2)
__device__ float      g_asrc2[Nn];
__device__ float      g_adst2[Nn];
__device__ unsigned   g_cnt[Nn];            // invariant: zero at kernel_launch entry
__device__ unsigned   g_off[Nn + 1];
__device__ unsigned   g_cur[Nn];
__device__ int        g_adj[ETMAX];         // CSR by dst: src node ids

__device__ __forceinline__ float lrelu(float a) { return a > 0.f ? a : 0.2f * a; }

// ------- layer-1: fused CSR-histogram + GEMM (smem weights) + att1 + fp16 ----
__global__ __launch_bounds__(256) void k_gemm1h(const float* __restrict__ x,
                                                const int* __restrict__ ei,
                                                const float* __restrict__ att_s,
                                                const float* __restrict__ att_d,
                                                int n, int E, int ET) {
    extern __shared__ float smem[];
    float* ws = smem;                 // [128 k][WS_STRIDE] transposed w1
    float* xs = smem + WS_FLOATS;     // [128 k][XS_STRIDE] x tile (32 nodes)
    int tid = threadIdx.x;
    int nb  = blockIdx.x * 32;

    // fire-and-forget CSR histogram (latency hides under the FFMA mainloop)
    for (int i = blockIdx.x * 256 + tid; i < ET; i += gridDim.x * 256) {
        int d = (i < E) ? ei[E + i] : (i - E);
        atomicAdd(&g_cnt[d], 1u);
    }

    // stage w1 transposed + x tile
    for (int idx = tid; idx < FIN * D1; idx += 256) {
        int c = idx >> 7, k = idx & 127;          // w1: [D1][FIN] row-major
        ws[k * WS_STRIDE + c] = x ? __ldg(&((const float*)att_s)[0]) * 0.f + __ldg(&((const float*)x)[0]) * 0.f + 0.f : 0.f; // placeholder overwritten below
    }
    // (real fill — separate loop keeps the compiler from aliasing tricks)
    {
        const float* w1 = (const float*)nullptr;  // unused; see k_gemm1h_w below
    }
    __syncthreads();
    (void)ws; (void)xs; (void)nb; (void)att_d;
}

// NOTE: the kernel above is replaced by the real one below; kept out of launch.

__global__ __launch_bounds__(256) void k_gemm1x(const float* __restrict__ x,
                                                const float* __restrict__ w1,
                                                const int* __restrict__ ei,
                                                const float* __restrict__ att_s,
                                                const float* __restrict__ att_d,
                                                int n, int E, int ET) {
    extern __shared__ float smem[];
    float* ws = smem;                 // [128 k][WS_STRIDE] transposed w1
    float* xs = smem + WS_FLOATS;     // [128 k][XS_STRIDE] x tile (32 nodes)
    int tid = threadIdx.x;
    int nb  = blockIdx.x * 32;

    // fire-and-forget CSR histogram
    for (int i = blockIdx.x * 256 + tid; i < ET; i += gridDim.x * 256) {
        int d = (i < E) ? ei[E + i] : (i - E);
        atomicAdd(&g_cnt[d], 1u);
    }

    // stage w1 transposed: coalesced LDG along k, STS stride WS_STRIDE
    for (int idx = tid; idx < FIN * D1; idx += 256) {
        int c = idx >> 7, k = idx & 127;          // w1: [D1][FIN] row-major
        ws[k * WS_STRIDE + c] = w1[c * FIN + k];
    }
    // stage x tile
    for (int idx = tid; idx < 32 * 128; idx += 256) {
        int node = idx >> 7, k = idx & 127;
        xs[k * XS_STRIDE + node] = (nb + node < n) ? x[(nb + node) * FIN + k] : 0.f;
    }
    __syncthreads();

    int c4 = tid & 31;     // channels c4*4 .. c4*4+3 (lane id)
    int ng = tid >> 5;     // nodes ng*4 .. ng*4+3 (warp id)
    float acc[4][4];
#pragma unroll
    for (int i = 0; i < 4; i++)
#pragma unroll
        for (int j = 0; j < 4; j++) acc[i][j] = 0.f;
#pragma unroll 8
    for (int k = 0; k < 128; k++) {
        float4 w = *(const float4*)&ws[k * WS_STRIDE + c4 * 4];
        float xv0 = xs[k * XS_STRIDE + ng * 4 + 0];
        float xv1 = xs[k * XS_STRIDE + ng * 4 + 1];
        float xv2 = xs[k * XS_STRIDE + ng * 4 + 2];
        float xv3 = xs[k * XS_STRIDE + ng * 4 + 3];
        acc[0][0] += xv0 * w.x; acc[0][1] += xv0 * w.y; acc[0][2] += xv0 * w.z; acc[0][3] += xv0 * w.w;
        acc[1][0] += xv1 * w.x; acc[1][1] += xv1 * w.y; acc[1][2] += xv1 * w.z; acc[1][3] += xv1 * w.w;
        acc[2][0] += xv2 * w.x; acc[2][1] += xv2 * w.y; acc[2][2] += xv2 * w.z; acc[2][3] += xv2 * w.w;
        acc[3][0] += xv3 * w.x; acc[3][1] += xv3 * w.y; acc[3][2] += xv3 * w.z; acc[3][3] += xv3 * w.w;
    }
    // fp16 gather payload
#pragma unroll
    for (int i = 0; i < 4; i++) {
        int node = nb + ng * 4 + i;
        if (node < n) {
            g_xw1h[node * 64 + c4 * 2 + 0] = __floats2half2_rn(acc[i][0], acc[i][1]);
            g_xw1h[node * 64 + c4 * 2 + 1] = __floats2half2_rn(acc[i][2], acc[i][3]);
        }
    }
    // fused attention dots: reduce within 16-lane halves (= heads)
    float4 as4 = *(const float4*)&att_s[c4 * 4];
    float4 ad4 = *(const float4*)&att_d[c4 * 4];
#pragma unroll
    for (int i = 0; i < 4; i++) {
        float ps = acc[i][0] * as4.x + acc[i][1] * as4.y + acc[i][2] * as4.z + acc[i][3] * as4.w;
        float pd = acc[i][0] * ad4.x + acc[i][1] * ad4.y + acc[i][2] * ad4.z + acc[i][3] * ad4.w;
#pragma unroll
        for (int o = 8; o >= 1; o >>= 1) {
            ps += __shfl_xor_sync(0xffffffffu, ps, o);
            pd += __shfl_xor_sync(0xffffffffu, pd, o);
        }
        int node = nb + ng * 4 + i;
        if ((c4 & 15) == 0 && node < n) {
            int h = c4 >> 4;
            g_asrc1[node * 2 + h] = ps;
            g_adst1[node * 2 + h] = pd;
        }
    }
}

// -------- scan (+ re-zero g_cnt) + w2 repack in idle lanes -------------------
__global__ void k_scan(const float* __restrict__ w2, int n) {
    __shared__ unsigned ssum[1024];
    int t = threadIdx.x;
    // w2 repack: [NC][D1] -> [k4][o] float4
    for (int i = t; i < NC * D1; i += 1024) {
        int o = i / D1, k = i % D1;
        ((float*)g_w2t4)[((k >> 2) * NC + o) * 4 + (k & 3)] = w2[i];
    }
    int chunk = (n + 1023) >> 10;
    int b = t * chunk;
    int e = min(b + chunk, n);
    unsigned sum = 0;
    for (int i = b; i < e; i++) sum += g_cnt[i];
    ssum[t] = sum;
    __syncthreads();
    for (int o = 1; o < 1024; o <<= 1) {
        unsigned v = (t >= o) ? ssum[t - o] : 0u;
        __syncthreads();
        ssum[t] += v;
        __syncthreads();
    }
    unsigned run = (t == 0) ? 0u : ssum[t - 1];
    for (int i = b; i < e; i++) {
        unsigned c = g_cnt[i];
        g_cnt[i] = 0u;                            // restore invariant
        g_off[i] = run;
        g_cur[i] = run;
        run += c;
    }
    if (t == 0) g_off[n] = ssum[1023];
}

__global__ void k_scatter(const int* __restrict__ ei, int E, int ET) {
    int e = blockIdx.x * blockDim.x + threadIdx.x;
    if (e >= ET) return;
    int s, d;
    if (e < E) { s = ei[e]; d = ei[E + e]; } else { s = d = e - E; }
    unsigned pos = atomicAdd(&g_cur[d], 1u);
    g_adj[pos] = s;
}

// ------- layer-1 fused softmax+aggregate: warp/dst, 16-edge pipelined chunks -
__global__ void k_edge1(const float* __restrict__ b1, int n) {
    int gt = blockIdx.x * blockDim.x + threadIdx.x;
    int d  = gt >> 5;
    if (d >= n) return;
    int lane = gt & 31, h = lane >> 4, sub = lane & 15;
    int beg = (int)g_off[d], end = (int)g_off[d + 1];
    float adh = g_adst1[d * 2 + h];
    float4 acc = make_float4(0.f, 0.f, 0.f, 0.f);
    float s = 0.f;
    // chunk 0: lanes 0-15 compute e(head0), lanes 16-31 e(head1), same 16 edges
    int base = beg;
    int msrc = 0; float ex = 0.f;
    {
        int i0 = base + sub;
        if (i0 < end) {
            msrc = g_adj[i0];
            ex = __expf(lrelu(g_asrc1[msrc * 2 + h] + adh));
        }
    }
    while (base < end) {
        int nbase = base + 16;
        int nsrc = 0; float nex = 0.f;
        if (nbase < end) {              // software-pipeline next chunk's dep chain
            int i1 = nbase + sub;
            if (i1 < end) {
                nsrc = g_adj[i1];
                nex = __expf(lrelu(g_asrc1[nsrc * 2 + h] + adh));
            }
        }
        s += ex;
        int cnt = min(16, end - base);
#pragma unroll 8
        for (int j = 0; j < cnt; j++) {
            int   src  = __shfl_sync(0xffffffffu, msrc, j);
            float coef = __shfl_sync(0xffffffffu, ex, j + (h << 4));
            uint2 p = *(const uint2*)&g_xw1h[src * 64 + lane * 2];
            float2 v01 = __half22float2(*(__half2*)&p.x);
            float2 v23 = __half22float2(*(__half2*)&p.y);
            acc.x += v01.x * coef; acc.y += v01.y * coef;
            acc.z += v23.x * coef; acc.w += v23.y * coef;
        }
        msrc = nsrc; ex = nex; base = nbase;
    }
#pragma unroll
    for (int o = 8; o >= 1; o >>= 1)    // per-half sums: lanes<16 -> s0, >=16 -> s1
        s += __shfl_xor_sync(0xffffffffu, s, o);
    float r = 1.f / (s + 1e-16f);
    float4 bb = *(const float4*)&b1[lane * 4];
    *(float4*)&g_out1[d * D1 + lane * 4] =
        make_float4(acc.x * r + bb.x, acc.y * r + bb.y, acc.z * r + bb.z, acc.w * r + bb.w);
}

// ---------------- layer-2 GEMM (relu fused on load) + att2 dots --------------
__global__ void k_gemm2(const float* __restrict__ att_s, const float* __restrict__ att_d, int n) {
    __shared__ float xs[8 * 132];
    int t  = threadIdx.x;            // 128 threads = 8 nodes x 16 outs
    int nb = blockIdx.x * 8;
#pragma unroll
    for (int i = 0; i < 8; i++) {
        int node = nb + i;
        float v = (node < n) ? g_out1[node * D1 + t] : 0.f;
        xs[i * 132 + t] = fmaxf(v, 0.f);     // relu
    }
    __syncthreads();
    int ni = t >> 4;
    int o  = t & 15;
    float a0 = 0.f, a1 = 0.f, a2 = 0.f, a3 = 0.f;
#pragma unroll
    for (int k4 = 0; k4 < D1 / 4; k4 += 4) {
#pragma unroll
        for (int u = 0; u < 4; u++) {
            float4 w  = g_w2t4[(k4 + u) * NC + o];
            float4 xv = *(const float4*)&xs[ni * 132 + (k4 + u) * 4];
            float p = xv.x * w.x + xv.y * w.y + xv.z * w.z + xv.w * w.w;
            if (u == 0) a0 += p; else if (u == 1) a1 += p; else if (u == 2) a2 += p; else a3 += p;
        }
    }
    float acc = (a0 + a1) + (a2 + a3);
    int node = nb + ni;
    if (node < n) g_xw2h[node * NC + o] = __float2half(acc);
    float ps = acc * att_s[o];
    float pd = acc * att_d[o];
#pragma unroll
    for (int j = 8; j >= 1; j >>= 1) {
        ps += __shfl_xor_sync(0xffffffffu, ps, j);
        pd += __shfl_xor_sync(0xffffffffu, pd, j);
    }
    if (o == 0 && node < n) { g_asrc2[node] = ps; g_adst2[node] = pd; }
}

// ---------------- layer-2 fused softmax+aggregate (warp per dst) -------------
__global__ void k_edge2(const float* __restrict__ b2, float* __restrict__ out, int n) {
    int gt = blockIdx.x * blockDim.x + threadIdx.x;
    int d  = gt >> 5;
    if (d >= n) return;
    int lane = gt & 31;
    int beg = (int)g_off[d], end = (int)g_off[d + 1];
    float add = g_adst2[d];
    int half = lane >> 4;
    int c    = lane & 15;
    float acc = 0.f, s = 0.f;
    for (int base = beg; base < end; base += 32) {
        int myi = base + lane;
        float ev = 0.f;
        int msrc = 0;
        if (myi < end) {
            msrc = g_adj[myi];
            ev = __expf(lrelu(g_asrc2[msrc] + add));
        }
        s += ev;
        int cnt = min(32, end - base);
#pragma unroll 4
        for (int j = 0; j < cnt; j += 2) {
            int jj = j + half;                  // lanes 0-15 edge j, 16-31 edge j+1
            int   src = __shfl_sync(0xffffffffu, msrc, jj & 31);
            float e   = __shfl_sync(0xffffffffu, ev, jj & 31);
            if (jj < cnt)
                acc += __half2float(g_xw2h[src * NC + c]) * e;
        }
    }
#pragma unroll
    for (int o = 16; o >= 1; o >>= 1)
        s += __shfl_xor_sync(0xffffffffu, s, o);
    acc += __shfl_xor_sync(0xffffffffu, acc, 16);
    if (half == 0) {
        float r = 1.f / (s + 1e-16f);
        out[d * NC + c] = acc * r + b2[c];
    }
}

// ---------------- launcher ----------------------------------------------------
extern "C" void kernel_launch(void* const* d_in, const int* in_sizes, int n_in,
                              void* d_out, int out_size) {
    const float* x   = (const float*)d_in[0];
    const int*   ei  = (const int*)d_in[1];      // int32
    const float* w1  = (const float*)d_in[2];
    const float* as1 = (const float*)d_in[3];
    const float* ad1 = (const float*)d_in[4];
    const float* b1  = (const float*)d_in[5];
    const float* w2  = (const float*)d_in[6];
    const float* as2 = (const float*)d_in[7];
    const float* ad2 = (const float*)d_in[8];
    const float* b2  = (const float*)d_in[9];
    float* out = (float*)d_out;

    int n  = in_sizes[0] / FIN;     // 50000
    int E  = in_sizes[1] / 2;       // 1600000
    int ET = E + n;                 // 1650000

    cudaFuncSetAttribute(k_gemm1x, cudaFuncAttributeMaxDynamicSharedMemorySize, GEMM1_SMEM);

    // launch 0: fused hist + gemm1 + att1 + fp16 payload
    k_gemm1x<<<(n + 31) / 32, 256, GEMM1_SMEM>>>(x, w1, ei, as1, ad1, n, E, ET);
    // launch 1: scan (+ g_cnt re-zero + w2 repack)
    k_scan<<<1, 1024>>>(w2, n);
    // launch 2: CSR scatter
    k_scatter<<<(ET + 255) / 256, 256>>>(ei, E, ET);
    // launch 3 (profiled): layer-1 softmax+aggregate
    k_edge1<<<(n * 32 + 255) / 256, 256>>>(b1, n);
    // layer 2
    k_gemm2<<<(n + 7) / 8, 128>>>(as2, ad2, n);
    k_edge2<<<(n * 32 + 255) / 256, 256>>>(b2, out, n);
}

// round 8
// speedup vs baseline: 1.2763x; 1.0973x over previous
#include <cuda_runtime.h>
#include <cuda_fp16.h>

// Problem constants (fixed shapes for this problem)
#define Nn    50000
#define FIN   128
#define D1    128           // H1*C1
#define NC    16
#define EMAX  1600000
#define ETMAX (EMAX + Nn)

// ---------------- scratch (device globals; no allocation allowed) ------------
__device__ float4     g_w1t[128 * 32];      // [k][c4] -> w1[c4*4+cc][k]
__device__ float4     g_w2t4[(D1 / 4) * NC];
__device__ __half2    g_xw1h[Nn * 64];      // fp16 gather payload (layer 1)
__device__ float      g_out1[Nn * D1];
__device__ float      g_asrc1[Nn * 2];
__device__ float      g_adst1[Nn * 2];
__device__ __half     g_xw2h[Nn * NC];      // fp16 gather payload (layer 2)
__device__ float      g_asrc2[Nn];
__device__ float      g_adst2[Nn];
__device__ unsigned   g_cnt[Nn];            // invariant: zero at kernel_launch entry
__device__ unsigned   g_off[Nn + 1];
__device__ unsigned   g_cur[Nn];
__device__ int        g_adj[ETMAX];         // CSR by dst: src node ids

__device__ __forceinline__ float lrelu(float a) { return a > 0.f ? a : 0.2f * a; }

// ---------------- tiny prep: weight repacks only -----------------------------
__global__ void k_prep(const float* __restrict__ w1, const float* __restrict__ w2) {
    int i = blockIdx.x * blockDim.x + threadIdx.x;
    if (i < FIN * D1) {
        int c = i / FIN, k = i % FIN;             // w1: [D1][FIN] row-major
        ((float*)g_w1t)[(k * 32 + (c >> 2)) * 4 + (c & 3)] = w1[i];
    }
    if (i < NC * D1) {
        int o = i / D1, k = i % D1;               // w2: [NC][D1]
        ((float*)g_w2t4)[((k >> 2) * NC + o) * 4 + (k & 3)] = w2[i];
    }
}

// ------- layer-1: fused hist + GEMM (global weights) + att1 + fp16 payload ---
__global__ __launch_bounds__(256) void k_gemm1(const float* __restrict__ x,
                                               const int* __restrict__ ei,
                                               const float* __restrict__ att_s,
                                               const float* __restrict__ att_d,
                                               int n, int E, int ET) {
    __shared__ float xs[128 * 33];
    int tid = threadIdx.x;
    int nb  = blockIdx.x * 32;

    // fire-and-forget CSR histogram; latency hides under the FFMA mainloop
    for (int i = blockIdx.x * 256 + tid; i < ET; i += gridDim.x * 256) {
        int d = (i < E) ? ei[E + i] : (i - E);
        atomicAdd(&g_cnt[d], 1u);
    }

    for (int idx = tid; idx < 32 * 128; idx += 256) {
        int node = idx >> 7, k = idx & 127;
        xs[k * 33 + node] = (nb + node < n) ? x[(nb + node) * FIN + k] : 0.f;
    }
    __syncthreads();
    int c4 = tid & 31;     // channels c4*4 .. c4*4+3 (lane id)
    int ng = tid >> 5;     // nodes ng*4 .. ng*4+3 (warp id)
    float acc[4][4];
#pragma unroll
    for (int i = 0; i < 4; i++)
#pragma unroll
        for (int j = 0; j < 4; j++) acc[i][j] = 0.f;
#pragma unroll 8
    for (int k = 0; k < 128; k++) {
        float4 w = g_w1t[k * 32 + c4];
        float xv0 = xs[k * 33 + ng * 4 + 0];
        float xv1 = xs[k * 33 + ng * 4 + 1];
        float xv2 = xs[k * 33 + ng * 4 + 2];
        float xv3 = xs[k * 33 + ng * 4 + 3];
        acc[0][0] += xv0 * w.x; acc[0][1] += xv0 * w.y; acc[0][2] += xv0 * w.z; acc[0][3] += xv0 * w.w;
        acc[1][0] += xv1 * w.x; acc[1][1] += xv1 * w.y; acc[1][2] += xv1 * w.z; acc[1][3] += xv1 * w.w;
        acc[2][0] += xv2 * w.x; acc[2][1] += xv2 * w.y; acc[2][2] += xv2 * w.z; acc[2][3] += xv2 * w.w;
        acc[3][0] += xv3 * w.x; acc[3][1] += xv3 * w.y; acc[3][2] += xv3 * w.z; acc[3][3] += xv3 * w.w;
    }
    // fp16 gather payload
#pragma unroll
    for (int i = 0; i < 4; i++) {
        int node = nb + ng * 4 + i;
        if (node < n) {
            g_xw1h[node * 64 + c4 * 2 + 0] = __floats2half2_rn(acc[i][0], acc[i][1]);
            g_xw1h[node * 64 + c4 * 2 + 1] = __floats2half2_rn(acc[i][2], acc[i][3]);
        }
    }
    // fused attention dots: reduce within 16-lane halves (= heads)
    float4 as4 = *(const float4*)&att_s[c4 * 4];
    float4 ad4 = *(const float4*)&att_d[c4 * 4];
#pragma unroll
    for (int i = 0; i < 4; i++) {
        float ps = acc[i][0] * as4.x + acc[i][1] * as4.y + acc[i][2] * as4.z + acc[i][3] * as4.w;
        float pd = acc[i][0] * ad4.x + acc[i][1] * ad4.y + acc[i][2] * ad4.z + acc[i][3] * ad4.w;
#pragma unroll
        for (int o = 8; o >= 1; o >>= 1) {
            ps += __shfl_xor_sync(0xffffffffu, ps, o);
            pd += __shfl_xor_sync(0xffffffffu, pd, o);
        }
        int node = nb + ng * 4 + i;
        if ((c4 & 15) == 0 && node < n) {
            int h = c4 >> 4;
            g_asrc1[node * 2 + h] = ps;
            g_adst1[node * 2 + h] = pd;
        }
    }
}

// -------- scan (+ re-zero g_cnt for next call) -------------------------------
__global__ void k_scan(int n) {
    __shared__ unsigned ssum[1024];
    int t = threadIdx.x;
    int chunk = (n + 1023) >> 10;
    int b = t * chunk;
    int e = min(b + chunk, n);
    unsigned sum = 0;
    for (int i = b; i < e; i++) sum += g_cnt[i];
    ssum[t] = sum;
    __syncthreads();
    for (int o = 1; o < 1024; o <<= 1) {
        unsigned v = (t >= o) ? ssum[t - o] : 0u;
        __syncthreads();
        ssum[t] += v;
        __syncthreads();
    }
    unsigned run = (t == 0) ? 0u : ssum[t - 1];
    for (int i = b; i < e; i++) {
        unsigned c = g_cnt[i];
        g_cnt[i] = 0u;                            // restore invariant
        g_off[i] = run;
        g_cur[i] = run;
        run += c;
    }
    if (t == 0) g_off[n] = ssum[1023];
}

__global__ void k_scatter(const int* __restrict__ ei, int E, int ET) {
    int e = blockIdx.x * blockDim.x + threadIdx.x;
    if (e >= ET) return;
    int s, d;
    if (e < E) { s = ei[e]; d = ei[E + e]; } else { s = d = e - E; }
    unsigned pos = atomicAdd(&g_cur[d], 1u);
    g_adj[pos] = s;
}

// ------- layer-1 fused softmax+aggregate: warp/dst, 16-edge pipelined chunks -
__global__ void k_edge1(const float* __restrict__ b1, int n) {
    int gt = blockIdx.x * blockDim.x + threadIdx.x;
    int d  = gt >> 5;
    if (d >= n) return;
    int lane = gt & 31, h = lane >> 4, sub = lane & 15;
    int beg = (int)g_off[d], end = (int)g_off[d + 1];
    float adh = g_adst1[d * 2 + h];
    float4 acc = make_float4(0.f, 0.f, 0.f, 0.f);
    float s = 0.f;
    // chunk 0: lanes 0-15 compute e(head0), lanes 16-31 e(head1), same 16 edges
    int base = beg;
    int msrc = 0; float ex = 0.f;
    {
        int i0 = base + sub;
        if (i0 < end) {
            msrc = g_adj[i0];
            ex = __expf(lrelu(g_asrc1[msrc * 2 + h] + adh));
        }
    }
    while (base < end) {
        int nbase = base + 16;
        int nsrc = 0; float nex = 0.f;
        if (nbase < end) {              // software-pipeline next chunk's dep chain
            int i1 = nbase + sub;
            if (i1 < end) {
                nsrc = g_adj[i1];
                nex = __expf(lrelu(g_asrc1[nsrc * 2 + h] + adh));
            }
        }
        s += ex;
        int cnt = min(16, end - base);
#pragma unroll 8
        for (int j = 0; j < cnt; j++) {
            int   src  = __shfl_sync(0xffffffffu, msrc, j);
            float coef = __shfl_sync(0xffffffffu, ex, j + (h << 4));
            uint2 p = *(const uint2*)&g_xw1h[src * 64 + lane * 2];
            float2 v01 = __half22float2(*(__half2*)&p.x);
            float2 v23 = __half22float2(*(__half2*)&p.y);
            acc.x += v01.x * coef; acc.y += v01.y * coef;
            acc.z += v23.x * coef; acc.w += v23.y * coef;
        }
        msrc = nsrc; ex = nex; base = nbase;
    }
#pragma unroll
    for (int o = 8; o >= 1; o >>= 1)    // per-half sums: lanes<16 -> s0, >=16 -> s1
        s += __shfl_xor_sync(0xffffffffu, s, o);
    float r = 1.f / (s + 1e-16f);
    float4 bb = *(const float4*)&b1[lane * 4];
    *(float4*)&g_out1[d * D1 + lane * 4] =
        make_float4(acc.x * r + bb.x, acc.y * r + bb.y, acc.z * r + bb.z, acc.w * r + bb.w);
}

// ---------------- layer-2 GEMM (relu fused on load) + att2 dots --------------
__global__ void k_gemm2(const float* __restrict__ att_s, const float* __restrict__ att_d, int n) {
    __shared__ float xs[8 * 132];
    int t  = threadIdx.x;            // 128 threads = 8 nodes x 16 outs
    int nb = blockIdx.x * 8;
#pragma unroll
    for (int i = 0; i < 8; i++) {
        int node = nb + i;
        float v = (node < n) ? g_out1[node * D1 + t] : 0.f;
        xs[i * 132 + t] = fmaxf(v, 0.f);     // relu
    }
    __syncthreads();
    int ni = t >> 4;
    int o  = t & 15;
    float a0 = 0.f, a1 = 0.f, a2 = 0.f, a3 = 0.f;
#pragma unroll
    for (int k4 = 0; k4 < D1 / 4; k4 += 4) {
#pragma unroll
        for (int u = 0; u < 4; u++) {
            float4 w  = g_w2t4[(k4 + u) * NC + o];
            float4 xv = *(const float4*)&xs[ni * 132 + (k4 + u) * 4];
            float p = xv.x * w.x + xv.y * w.y + xv.z * w.z + xv.w * w.w;
            if (u == 0) a0 += p; else if (u == 1) a1 += p; else if (u == 2) a2 += p; else a3 += p;
        }
    }
    float acc = (a0 + a1) + (a2 + a3);
    int node = nb + ni;
    if (node < n) g_xw2h[node * NC + o] = __float2half(acc);
    float ps = acc * att_s[o];
    float pd = acc * att_d[o];
#pragma unroll
    for (int j = 8; j >= 1; j >>= 1) {
        ps += __shfl_xor_sync(0xffffffffu, ps, j);
        pd += __shfl_xor_sync(0xffffffffu, pd, j);
    }
    if (o == 0 && node < n) { g_asrc2[node] = ps; g_adst2[node] = pd; }
}

// ---------------- layer-2 fused softmax+aggregate (warp per dst) -------------
__global__ void k_edge2(const float* __restrict__ b2, float* __restrict__ out, int n) {
    int gt = blockIdx.x * blockDim.x + threadIdx.x;
    int d  = gt >> 5;
    if (d >= n) return;
    int lane = gt & 31;
    int beg = (int)g_off[d], end = (int)g_off[d + 1];
    float add = g_adst2[d];
    int half = lane >> 4;
    int c    = lane & 15;
    float acc = 0.f, s = 0.f;
    for (int base = beg; base < end; base += 32) {
        int myi = base + lane;
        float ev = 0.f;
        int msrc = 0;
        if (myi < end) {
            msrc = g_adj[myi];
            ev = __expf(lrelu(g_asrc2[msrc] + add));
        }
        s += ev;
        int cnt = min(32, end - base);
#pragma unroll 4
        for (int j = 0; j < cnt; j += 2) {
            int jj = j + half;                  // lanes 0-15 edge j, 16-31 edge j+1
            int   src = __shfl_sync(0xffffffffu, msrc, jj & 31);
            float e   = __shfl_sync(0xffffffffu, ev, jj & 31);
            if (jj < cnt)
                acc += __half2float(g_xw2h[src * NC + c]) * e;
        }
    }
#pragma unroll
    for (int o = 16; o >= 1; o >>= 1)
        s += __shfl_xor_sync(0xffffffffu, s, o);
    acc += __shfl_xor_sync(0xffffffffu, acc, 16);
    if (half == 0) {
        float r = 1.f / (s + 1e-16f);
        out[d * NC + c] = acc * r + b2[c];
    }
}

// ---------------- launcher ----------------------------------------------------
extern "C" void kernel_launch(void* const* d_in, const int* in_sizes, int n_in,
                              void* d_out, int out_size) {
    const float* x   = (const float*)d_in[0];
    const int*   ei  = (const int*)d_in[1];      // int32
    const float* w1  = (const float*)d_in[2];
    const float* as1 = (const float*)d_in[3];
    const float* ad1 = (const float*)d_in[4];
    const float* b1  = (const float*)d_in[5];
    const float* w2  = (const float*)d_in[6];
    const float* as2 = (const float*)d_in[7];
    const float* ad2 = (const float*)d_in[8];
    const float* b2  = (const float*)d_in[9];
    float* out = (float*)d_out;

    int n  = in_sizes[0] / FIN;     // 50000
    int E  = in_sizes[1] / 2;       // 1600000
    int ET = E + n;                 // 1650000

    // 0: tiny weight repack
    k_prep<<<(FIN * D1 + 255) / 256, 256>>>(w1, w2);
    // 1: fused hist + gemm1 + att1 + fp16 payload
    k_gemm1<<<(n + 31) / 32, 256>>>(x, ei, as1, ad1, n, E, ET);
    // 2: scan (+ g_cnt re-zero)
    k_scan<<<1, 1024>>>(n);
    // 3 (profiled): CSR scatter
    k_scatter<<<(ET + 255) / 256, 256>>>(ei, E, ET);
    // layer-1 softmax+aggregate
    k_edge1<<<(n * 32 + 255) / 256, 256>>>(b1, n);
    // layer 2
    k_gemm2<<<(n + 7) / 8, 128>>>(as2, ad2, n);
    k_edge2<<<(n * 32 + 255) / 256, 256>>>(b2, out, n);
}